// round 15
// baseline (speedup 1.0000x reference)
#include <cuda_runtime.h>
#include <cuda_bf16.h>
#include <cstdint>

// Embedding gather: out[token, :] = W[:, ids[token]], W row-major [D_MODEL, VOCAB].
// R15: R14 was grid-limited (393 blocks / 148 SMs = 2.66/SM, so the 4-block
// occupancy allowance went unused). Split each tile into 2 blocks along D
// (16 chunks each) -> grid 786 -> ~4 blocks/SM -> occ ~85%. Inner loop is
// R14's proven 32-reg shape.

#define VOCAB     50257
#define D_MODEL   1024
#define N_TOK     (4 * 4096)

#define TILE_C    128
#define TILE_BITS 7
#define N_TILES   ((VOCAB + TILE_C - 1) / TILE_C)   // 393
#define TILE_D    32
#define D_SPLIT   2
#define CHUNKS_PER_BLOCK (D_MODEL / TILE_D / D_SPLIT)  // 16
#define PAD       (TILE_C + 1)                      // 129: conflict-free
#define STAGE_ELEMS (TILE_D * PAD)                  // 4128 floats
#define CAP       1024
#define NTHREADS  512

__global__ __launch_bounds__(NTHREADS, 4)
void gather_tile_kernel(const int* __restrict__ ids,
                        const float* __restrict__ W,
                        float* __restrict__ out) {
    // Adjacent blocks = the two D-halves of one tile (good id-array L2 reuse).
    const int tile = blockIdx.x >> 1;
    const int half = blockIdx.x & 1;
    const int dbase = half * (CHUNKS_PER_BLOCK * TILE_D);   // 0 or 512

    __shared__ float buf[2][STAGE_ELEMS];   // 33 KB
    __shared__ int   s_list[CAP];           // 4 KB
    __shared__ int   s_cnt;

    const int tid  = threadIdx.x;
    const int lane = tid & 31;
    const int wid  = tid >> 5;                 // 16 warps
    const int c0   = tile * TILE_C;

    // Load mapping: lc = column 0..127, lr = row-phase 0..3. Thread loads
    // rows {p*4+lr : p=0..7} of each 32-row chunk at column gcol.
    const int lc = tid & (TILE_C - 1);
    const int lr = tid >> TILE_BITS;
    const int gcol = min(c0 + lc, VOCAB - 1);  // clamp: last tile only

    // Single running pointer; in-chunk row offsets are compile-time
    // immediates (p * 4 * VOCAB elements) -> ~1 live long for addressing.
    const float* bp = W + (long)(dbase + lr) * VOCAB + gcol;   // first chunk
    const float* bq = bp + 32L * VOCAB;                        // next chunk

    if (tid == 0) s_cnt = 0;

    float rcur[8], rnext[8];

    // Prologue: first-chunk loads; the id-filter runs in their shadow.
    #pragma unroll
    for (int p = 0; p < 8; p++)
        rcur[p] = __ldg(bp + (long)p * 4 * VOCAB);

    __syncthreads();   // s_cnt = 0 visible

    // Filter: find tokens whose id falls in this tile. Order irrelevant.
    const int4* __restrict__ ids4 = (const int4*)ids;
    for (int i = tid; i < N_TOK / 4; i += NTHREADS) {
        const int4 v = ids4[i];
        const int base_tok = i * 4;
        #pragma unroll
        for (int k = 0; k < 4; k++) {
            const int id = (&v.x)[k];
            if ((id >> TILE_BITS) == tile) {
                const int pos = atomicAdd(&s_cnt, 1);
                if (pos < CAP)
                    s_list[pos] = ((id & (TILE_C - 1)) << 16) | (base_tok + k);
            }
        }
    }
    __syncthreads();

    const int cnt = s_cnt;
    if (cnt == 0) return;                      // uniform block exit
    const bool overflow = (cnt > CAP);
    const int n = overflow ? 0 : cnt;

    for (int c = 0; c < CHUNKS_PER_BLOCK; c++) {
        // Issue next chunk's loads early (consumed next iteration).
        if (c + 1 < CHUNKS_PER_BLOCK) {
            #pragma unroll
            for (int p = 0; p < 8; p++)
                rnext[p] = __ldg(bq + (long)p * 4 * VOCAB);
            bq += 32L * VOCAB;
        }

        // Stage chunk c to smem. Safe: buf[c&1] last distributed in iter c-2;
        // every warp passed iter c-1's barrier before this STS.
        float* sstage = &buf[c & 1][0];
        #pragma unroll
        for (int p = 0; p < 8; p++)
            sstage[(p * 4 + lr) * PAD + lc] = rcur[p];
        __syncthreads();

        // Distribute chunk c: row = lane -> one coalesced 128B store/token.
        const int d0 = dbase + c * TILE_D;
        for (int s = wid; s < n; s += 16) {
            const int pk    = s_list[s];
            const int col   = pk >> 16;
            const int token = pk & 0xFFFF;
            out[(long)token * D_MODEL + d0 + lane] = sstage[lane * PAD + col];
        }
        if (overflow) {
            // Correct-for-any-input fallback (never taken here; idempotent).
            for (int s = wid; s < N_TOK; s += 16) {
                const int id = __ldg(&ids[s]);
                if ((id >> TILE_BITS) == tile)
                    out[(long)s * D_MODEL + d0 + lane] =
                        sstage[lane * PAD + (id & (TILE_C - 1))];
            }
        }

        #pragma unroll
        for (int p = 0; p < 8; p++) rcur[p] = rnext[p];
    }
}

extern "C" void kernel_launch(void* const* d_in, const int* in_sizes, int n_in,
                              void* d_out, int out_size) {
    const int* ids = nullptr;
    const float* W = nullptr;
    for (int i = 0; i < n_in; i++) {
        if (in_sizes[i] == N_TOK) ids = (const int*)d_in[i];
        else if (in_sizes[i] == D_MODEL * VOCAB) W = (const float*)d_in[i];
    }
    float* out = (float*)d_out;

    gather_tile_kernel<<<N_TILES * D_SPLIT, NTHREADS>>>(ids, W, out);
}

// round 16
// speedup vs baseline: 1.0454x; 1.0454x over previous
#include <cuda_runtime.h>
#include <cuda_bf16.h>
#include <cstdint>

// Embedding gather: out[token, :] = W[:, ids[token]], W row-major [D_MODEL, VOCAB].
// R16: R14 (best structure; ~5.3TB/s = measured pattern ceiling) + sector
// skipping: only ~89% of each tile's 32B sectors contain any requested
// column (P_empty = (1-8/128)^~35 ~ 11%). The filter builds a 16-bit
// used-sector mask; loads are predicated on one constant bit per thread.
// Cuts W reads ~11% (~22MB). W loads use __ldcs (read-once, evict-first).

#define VOCAB     50257
#define D_MODEL   1024
#define N_TOK     (4 * 4096)

#define TILE_C    128
#define TILE_BITS 7
#define N_TILES   ((VOCAB + TILE_C - 1) / TILE_C)   // 393
#define TILE_D    32
#define N_CHUNK   (D_MODEL / TILE_D)                // 32
#define PAD       (TILE_C + 1)                      // 129: conflict-free
#define STAGE_ELEMS (TILE_D * PAD)                  // 4128 floats
#define CAP       512                               // max tokens/tile ~75 here
#define NTHREADS  512

__global__ __launch_bounds__(NTHREADS, 4)
void gather_tile_kernel(const int* __restrict__ ids,
                        const float* __restrict__ W,
                        float* __restrict__ out) {
    const int tile = blockIdx.x;

    __shared__ float buf[2][STAGE_ELEMS];   // 33 KB
    __shared__ int   s_list[CAP];           // 2 KB
    __shared__ int   s_cnt;
    __shared__ int   s_secmask;             // bit k: sector k (cols 8k..8k+7) used

    const int tid  = threadIdx.x;
    const int lane = tid & 31;
    const int wid  = tid >> 5;                 // 16 warps
    const int c0   = tile * TILE_C;

    // Load mapping: lc = column 0..127, lr = row-phase 0..3. Thread loads
    // rows {p*4+lr : p=0..7} of each 32-row chunk at column gcol.
    const int lc = tid & (TILE_C - 1);
    const int lr = tid >> TILE_BITS;
    const int gcol = min(c0 + lc, VOCAB - 1);  // clamp: last tile only

    // Single running pointer; in-chunk row offsets are compile-time
    // immediates (p * 4 * VOCAB elements).
    const float* bp = W + (long)lr * VOCAB + gcol;        // chunk 0
    const float* bq = bp + 32L * VOCAB;                   // chunk 1 onward

    if (tid == 0) { s_cnt = 0; s_secmask = 0; }

    float rcur[8], rnext[8];

    // Prologue: chunk-0 loads (unpredicated -- mask not known yet); the
    // id-filter runs in their shadow.
    #pragma unroll
    for (int p = 0; p < 8; p++)
        rcur[p] = __ldcs(bp + (long)p * 4 * VOCAB);

    __syncthreads();   // s_cnt / s_secmask init visible

    // Filter: find tokens whose id falls in this tile; record used sectors.
    const int4* __restrict__ ids4 = (const int4*)ids;
    for (int i = tid; i < N_TOK / 4; i += NTHREADS) {
        const int4 v = ids4[i];
        const int base_tok = i * 4;
        #pragma unroll
        for (int k = 0; k < 4; k++) {
            const int id = (&v.x)[k];
            if ((id >> TILE_BITS) == tile) {
                const int col = id & (TILE_C - 1);
                atomicOr(&s_secmask, 1 << (col >> 3));   // before CAP check
                const int pos = atomicAdd(&s_cnt, 1);
                if (pos < CAP)
                    s_list[pos] = (col << 16) | (base_tok + k);
            }
        }
    }
    __syncthreads();

    const int cnt = s_cnt;
    if (cnt == 0) return;                      // uniform block exit
    const bool overflow = (cnt > CAP);
    const int n = overflow ? 0 : cnt;
    // Constant per thread: does my column's 8-float sector matter?
    const bool active = (s_secmask >> (lc >> 3)) & 1;

    for (int c = 0; c < N_CHUNK; c++) {
        // Issue chunk c+1 loads early, skipping unused sectors (~11%).
        if (c + 1 < N_CHUNK) {
            if (active) {
                #pragma unroll
                for (int p = 0; p < 8; p++)
                    rnext[p] = __ldcs(bq + (long)p * 4 * VOCAB);
            }
            bq += 32L * VOCAB;
        }

        // Stage chunk c to smem. Safe: buf[c&1] last distributed in iter c-2;
        // every warp passed iter c-1's barrier before this STS. Inactive
        // threads store stale regs -- those smem cells are never read.
        float* sstage = &buf[c & 1][0];
        #pragma unroll
        for (int p = 0; p < 8; p++)
            sstage[(p * 4 + lr) * PAD + lc] = rcur[p];
        __syncthreads();

        // Distribute chunk c: row = lane -> one coalesced 128B store/token.
        const int d0 = c * TILE_D;
        for (int s = wid; s < n; s += 16) {
            const int pk    = s_list[s];
            const int col   = pk >> 16;
            const int token = pk & 0xFFFF;
            out[(long)token * D_MODEL + d0 + lane] = sstage[lane * PAD + col];
        }
        if (overflow) {
            // Correct-for-any-input fallback (never taken here; idempotent).
            // Mask is complete (atomicOr precedes CAP check), so sectors for
            // all tokens were loaded.
            for (int s = wid; s < N_TOK; s += 16) {
                const int id = __ldg(&ids[s]);
                if ((id >> TILE_BITS) == tile)
                    out[(long)s * D_MODEL + d0 + lane] =
                        sstage[lane * PAD + (id & (TILE_C - 1))];
            }
        }

        #pragma unroll
        for (int p = 0; p < 8; p++) rcur[p] = rnext[p];
    }
}

extern "C" void kernel_launch(void* const* d_in, const int* in_sizes, int n_in,
                              void* d_out, int out_size) {
    const int* ids = nullptr;
    const float* W = nullptr;
    for (int i = 0; i < n_in; i++) {
        if (in_sizes[i] == N_TOK) ids = (const int*)d_in[i];
        else if (in_sizes[i] == D_MODEL * VOCAB) W = (const float*)d_in[i];
    }
    float* out = (float*)d_out;

    gather_tile_kernel<<<N_TILES, NTHREADS>>>(ids, W, out);
}